// round 17
// baseline (speedup 1.0000x reference)
#include <cuda_runtime.h>
#include <cuda_bf16.h>
#include <stdint.h>

// ---------------- problem constants (shapes fixed by the dataset) -----------
#define MAXN 100000
#define MAXE 1600000
#define IN_C 128
#define HID_C 128
#define OUT_C 64
#define SCAN_BT 1024

// ---------------- device scratch (no allocs; referenced directly) -----------
// g_deg / g_cnt are zero at module load; cleanup_kernel restores them to zero
// every call (off the critical path), keeping kernel_launch deterministic.
__device__ __align__(16) float g_deg [MAXN];
__device__ __align__(16) float g_dinv[MAXN];
__device__ __align__(16) int   g_cnt [MAXN];
__device__ __align__(16) int   g_cur [MAXN];
__device__ __align__(16) int   g_off [MAXN + 1];
__device__ __align__(16) int   g_bsum[128];
__device__ __align__(16) int2  g_csr [MAXE];          // (src, w-as-bits)
__device__ __align__(16) float g_h1[(size_t)MAXN * HID_C];
__device__ __align__(16) float g_a1[(size_t)MAXN * HID_C];
__device__ __align__(16) float g_h2[(size_t)MAXN * OUT_C];
__device__ __align__(16) float g_z [(size_t)MAXN * OUT_C];

// ---------------- degree + in-edge counting (2 edges/thread) -----------------
__global__ void deg_cnt_kernel(const int* __restrict__ dst,
                               const float* __restrict__ ew, int ne) {
    int t = blockIdx.x * blockDim.x + threadIdx.x;
    int e = t * 2;
    if (e + 1 < ne) {
        int2   d2 = *(const int2*)(dst + e);
        float2 w2 = *(const float2*)(ew + e);
        atomicAdd(&g_deg[d2.x], w2.x);
        atomicAdd(&g_cnt[d2.x], 1);
        atomicAdd(&g_deg[d2.y], w2.y);
        atomicAdd(&g_cnt[d2.y], 1);
    } else if (e < ne) {
        atomicAdd(&g_deg[dst[e]], ew[e]);
        atomicAdd(&g_cnt[dst[e]], 1);
    }
}

// ---------------- scan pass A: dinv + per-block sums of cnt -----------------
__global__ void scanA_kernel(int n) {
    __shared__ int wsum[32];
    int tid = threadIdx.x;
    int i = blockIdx.x * SCAN_BT + tid;
    int v = 0;
    if (i < n) {
        v = g_cnt[i];
        g_dinv[i] = rsqrtf(g_deg[i] + 1.0f);   // +1 = self-loop weight
    }
    int s = v;
#pragma unroll
    for (int o = 16; o > 0; o >>= 1) s += __shfl_down_sync(0xffffffffu, s, o);
    if ((tid & 31) == 0) wsum[tid >> 5] = s;
    __syncthreads();
    if (tid < 32) {
        int t = wsum[tid];
#pragma unroll
        for (int o = 16; o > 0; o >>= 1) t += __shfl_down_sync(0xffffffffu, t, o);
        if (tid == 0) g_bsum[blockIdx.x] = t;
    }
}

// ---------------- scan pass B: full exclusive scan -> g_off, g_cur ----------
__global__ void scanB_kernel(int n, int nb) {
    __shared__ int bsh[128];
    __shared__ int wpre[32];
    int tid = threadIdx.x;
    int lane = tid & 31;
    int wid = tid >> 5;

    if (tid < 128) bsh[tid] = (tid < nb) ? g_bsum[tid] : 0;
    __syncthreads();
#pragma unroll
    for (int o = 1; o < 128; o <<= 1) {
        int y = 0;
        if (tid >= o && tid < 128) y = bsh[tid - o];
        __syncthreads();
        if (tid >= o && tid < 128) bsh[tid] += y;
        __syncthreads();
    }
    int bpre = bsh[blockIdx.x] - g_bsum[blockIdx.x];   // exclusive block prefix

    int i = blockIdx.x * SCAN_BT + tid;
    int v = (i < n) ? g_cnt[i] : 0;
    int x = v;
#pragma unroll
    for (int o = 1; o < 32; o <<= 1) {
        int y = __shfl_up_sync(0xffffffffu, x, o);
        if (lane >= o) x += y;
    }
    if (lane == 31) wpre[wid] = x;
    __syncthreads();
    if (wid == 0) {
        int t = wpre[lane];
        int tv = t;
#pragma unroll
        for (int o = 1; o < 32; o <<= 1) {
            int y = __shfl_up_sync(0xffffffffu, tv, o);
            if (lane >= o) tv += y;
        }
        wpre[lane] = tv - t;
    }
    __syncthreads();
    int excl = bpre + wpre[wid] + (x - v);
    if (i < n) {
        g_off[i] = excl;
        g_cur[i] = excl;
        if (i == n - 1) g_off[n] = excl + v;
    }
}

// fill CSR: (src, w) pairs grouped by dst (2 edges/thread)
__global__ void fill_kernel(const int* __restrict__ src,
                            const int* __restrict__ dst,
                            const float* __restrict__ ew, int ne) {
    int t = blockIdx.x * blockDim.x + threadIdx.x;
    int e = t * 2;
    if (e + 1 < ne) {
        int2   s2 = *(const int2*)(src + e);
        int2   d2 = *(const int2*)(dst + e);
        float2 w2 = *(const float2*)(ew + e);
        int slot0 = atomicAdd(&g_cur[d2.x], 1);
        g_csr[slot0] = make_int2(s2.x, __float_as_int(g_dinv[s2.x] * w2.x * g_dinv[d2.x]));
        int slot1 = atomicAdd(&g_cur[d2.y], 1);
        g_csr[slot1] = make_int2(s2.y, __float_as_int(g_dinv[s2.y] * w2.y * g_dinv[d2.y]));
    } else if (e < ne) {
        int s = src[e];
        int d = dst[e];
        int slot = atomicAdd(&g_cur[d], 1);
        g_csr[slot] = make_int2(s, __float_as_int(g_dinv[s] * ew[e] * g_dinv[d]));
    }
}

// restore scratch counters to zero for the next call (determinism)
__global__ void cleanup_kernel(int n) {
    int i = blockIdx.x * blockDim.x + threadIdx.x;
    if (i < n) { g_deg[i] = 0.0f; g_cnt[i] = 0; }
}

// ---------------- tiled FP32 GEMM, 8x8 register blocking, KC=32 --------------
// C[nrows, NOUT] = A[nrows,128] @ W[128,NOUT]
// Tile: 128 rows x NOUT cols, 256 threads, K-chunk 32, A staged transposed.
// LAYER 1: A = X (arg), C = g_h1.  LAYER 2: A = relu(g_a1+b1), C = g_h2.
template<int NOUT, int LAYER>
__global__ __launch_bounds__(256) void gemm_kernel(const float* __restrict__ X,
                                                   const float* __restrict__ W,
                                                   const float* __restrict__ bias_in,
                                                   int nrows) {
    const float* __restrict__ A = (LAYER == 1) ? X : (const float*)g_a1;
    float* __restrict__ C = (LAYER == 1) ? g_h1 : g_h2;

    constexpr int KC  = 32;
    constexpr int TX  = NOUT / 8;            // threads in col dir (16 or 8)
    constexpr int TY  = 256 / TX;            // threads in row dir (16 or 32)
    constexpr int RPT = 128 / TY;            // rows per thread (8 or 4)
    constexpr int APAD = 4;

    __shared__ float As[KC][128 + APAD];     // transposed: As[k][row]
    __shared__ float Bs[KC][NOUT];

    int tid = threadIdx.x;
    int tx = tid % TX, ty = tid / TX;
    int row0 = blockIdx.x * 128;
    int rbase = ty * RPT;
    int cbase = tx * 8;

    float acc[RPT][8];
#pragma unroll
    for (int i = 0; i < RPT; i++)
#pragma unroll
        for (int j = 0; j < 8; j++) acc[i][j] = 0.0f;

    for (int k0 = 0; k0 < 128; k0 += KC) {
        // A chunk: 128 rows x 32 k = 1024 float4, 4 per thread; store transposed
#pragma unroll
        for (int i = 0; i < 4; i++) {
            int idx = tid + i * 256;         // 0..1023
            int r  = idx >> 3;               // 0..127
            int kc = (idx & 7) * 4;          // 0..28
            float4 v = make_float4(0.f, 0.f, 0.f, 0.f);
            int row = row0 + r;
            if (row < nrows) {
                v = *(const float4*)(A + (size_t)row * 128 + k0 + kc);
                if (LAYER == 2) {
                    float4 b = *(const float4*)(bias_in + k0 + kc);
                    v.x = fmaxf(v.x + b.x, 0.0f);
                    v.y = fmaxf(v.y + b.y, 0.0f);
                    v.z = fmaxf(v.z + b.z, 0.0f);
                    v.w = fmaxf(v.w + b.w, 0.0f);
                }
            }
            As[kc + 0][r] = v.x; As[kc + 1][r] = v.y;
            As[kc + 2][r] = v.z; As[kc + 3][r] = v.w;
        }
        // B chunk: 32 rows x NOUT cols
        constexpr int BV = KC * NOUT / 4 / 256;   // float4/thread (4 or 2)
#pragma unroll
        for (int i = 0; i < BV; i++) {
            int idx = tid + i * 256;
            int r  = idx / (NOUT / 4);
            int c4 = (idx % (NOUT / 4)) * 4;
            *(float4*)&Bs[r][c4] = *(const float4*)(W + (size_t)(k0 + r) * NOUT + c4);
        }
        __syncthreads();

#pragma unroll
        for (int k = 0; k < KC; k++) {
            float a[RPT], b[8];
#pragma unroll
            for (int i = 0; i < RPT; i += 4)
                *(float4*)&a[i] = *(const float4*)&As[k][rbase + i];
            *(float4*)&b[0] = *(const float4*)&Bs[k][cbase];
            *(float4*)&b[4] = *(const float4*)&Bs[k][cbase + 4];
#pragma unroll
            for (int i = 0; i < RPT; i++)
#pragma unroll
                for (int j = 0; j < 8; j++)
                    acc[i][j] += a[i] * b[j];
        }
        __syncthreads();
    }

#pragma unroll
    for (int i = 0; i < RPT; i++) {
        int row = row0 + rbase + i;
        if (row < nrows) {
            float* cp = C + (size_t)row * NOUT + cbase;
            *(float4*)(cp)     = make_float4(acc[i][0], acc[i][1], acc[i][2], acc[i][3]);
            *(float4*)(cp + 4) = make_float4(acc[i][4], acc[i][5], acc[i][6], acc[i][7]);
        }
    }
}

// ---------------- CSR gather aggregation: warp per dst node ------------------
// Out[n] = H[n]*dinv[n]^2 + sum_{in-edges e} w_e * H[src_e]
template<int FEAT, int LAYER>
__global__ void gather_kernel(int n) {
    const float* __restrict__ H = (LAYER == 1) ? g_h1 : g_h2;
    float* __restrict__ Out = (LAYER == 1) ? g_a1 : g_z;
    constexpr int VW = FEAT / 32;            // floats per lane (4 or 2)

    int t = blockIdx.x * blockDim.x + threadIdx.x;
    int node = t >> 5;
    int lane = t & 31;
    if (node >= n) return;

    float di = g_dinv[node];
    float sc = di * di;

    float acc[VW];
    {
        const float* hp = H + (size_t)node * FEAT + lane * VW;
        if constexpr (VW == 4) {
            float4 f = *(const float4*)hp;
            acc[0] = f.x * sc; acc[1] = f.y * sc; acc[2] = f.z * sc; acc[3] = f.w * sc;
        } else {
            float2 f = *(const float2*)hp;
            acc[0] = f.x * sc; acc[1] = f.y * sc;
        }
    }

    int i   = g_off[node];
    int end = g_off[node + 1];

    for (; i + 4 <= end; i += 4) {
        int2 c0 = g_csr[i];
        int2 c1 = g_csr[i + 1];
        int2 c2 = g_csr[i + 2];
        int2 c3 = g_csr[i + 3];
        const float* p0 = H + (size_t)c0.x * FEAT + lane * VW;
        const float* p1 = H + (size_t)c1.x * FEAT + lane * VW;
        const float* p2 = H + (size_t)c2.x * FEAT + lane * VW;
        const float* p3 = H + (size_t)c3.x * FEAT + lane * VW;
        float w0 = __int_as_float(c0.y), w1 = __int_as_float(c1.y);
        float w2 = __int_as_float(c2.y), w3 = __int_as_float(c3.y);
        if constexpr (VW == 4) {
            float4 v0 = *(const float4*)p0;
            float4 v1 = *(const float4*)p1;
            float4 v2 = *(const float4*)p2;
            float4 v3 = *(const float4*)p3;
            acc[0] += v0.x * w0 + v1.x * w1 + v2.x * w2 + v3.x * w3;
            acc[1] += v0.y * w0 + v1.y * w1 + v2.y * w2 + v3.y * w3;
            acc[2] += v0.z * w0 + v1.z * w1 + v2.z * w2 + v3.z * w3;
            acc[3] += v0.w * w0 + v1.w * w1 + v2.w * w2 + v3.w * w3;
        } else {
            float2 v0 = *(const float2*)p0;
            float2 v1 = *(const float2*)p1;
            float2 v2 = *(const float2*)p2;
            float2 v3 = *(const float2*)p3;
            acc[0] += v0.x * w0 + v1.x * w1 + v2.x * w2 + v3.x * w3;
            acc[1] += v0.y * w0 + v1.y * w1 + v2.y * w2 + v3.y * w3;
        }
    }
    for (; i < end; i++) {
        int2 c = g_csr[i];
        float w = __int_as_float(c.y);
        const float* p = H + (size_t)c.x * FEAT + lane * VW;
        if constexpr (VW == 4) {
            float4 v = *(const float4*)p;
            acc[0] += v.x * w; acc[1] += v.y * w;
            acc[2] += v.z * w; acc[3] += v.w * w;
        } else {
            float2 v = *(const float2*)p;
            acc[0] += v.x * w; acc[1] += v.y * w;
        }
    }

    float* op = Out + (size_t)node * FEAT + lane * VW;
    if constexpr (VW == 4)
        *(float4*)op = make_float4(acc[0], acc[1], acc[2], acc[3]);
    else
        *(float2*)op = make_float2(acc[0], acc[1]);
}

// ---------------- decode: out[e] = dot(z[a]+b2, z[b]+b2) over 64 dims --------
__global__ void decode_kernel(const int* __restrict__ ea,
                              const int* __restrict__ eb,
                              const float* __restrict__ b2,
                              float* __restrict__ out, int ne) {
    long long t = (long long)blockIdx.x * blockDim.x + threadIdx.x;
    int e = (int)(t >> 5);
    int lane = (int)(t & 31);
    if (e >= ne) return;
    int a = ea[e];
    int b = eb[e];
    float2 bb = *(const float2*)(b2 + lane * 2);
    float2 va = *(const float2*)(g_z + (size_t)a * 64 + lane * 2);
    float2 vb = *(const float2*)(g_z + (size_t)b * 64 + lane * 2);
    va.x += bb.x; va.y += bb.y;
    vb.x += bb.x; vb.y += bb.y;
    float p = va.x * vb.x + va.y * vb.y;
#pragma unroll
    for (int o = 16; o > 0; o >>= 1) p += __shfl_down_sync(0xffffffffu, p, o);
    if (lane == 0) out[e] = p;
}

// ---------------- host launch ------------------------------------------------
static inline int cdiv_ll(long long a, int b) { return (int)((a + b - 1) / b); }

extern "C" void kernel_launch(void* const* d_in, const int* in_sizes, int n_in,
                              void* d_out, int out_size) {
    const float* x   = (const float*)d_in[0];
    const int*   ei  = (const int*)d_in[1];    // [2, E] int32
    const float* ew  = (const float*)d_in[2];
    const int*   eli = (const int*)d_in[3];    // [2, EL] int32
    const float* W1  = (const float*)d_in[4];
    const float* b1  = (const float*)d_in[5];
    const float* W2  = (const float*)d_in[6];
    const float* b2  = (const float*)d_in[7];
    float*       out = (float*)d_out;

    const int N  = in_sizes[0] / IN_C;
    const int E  = in_sizes[1] / 2;
    const int EL = in_sizes[3] / 2;

    const int* src = ei;
    const int* dst = ei + E;
    const int* ea  = eli;
    const int* eb  = eli + EL;

    const int T = 256;
    const int nb = (N + SCAN_BT - 1) / SCAN_BT;

    static cudaStream_t s2 = nullptr;
    static cudaEvent_t evA = nullptr, evB = nullptr, evC = nullptr;
    if (s2 == nullptr) {
        cudaStreamCreateWithFlags(&s2, cudaStreamNonBlocking);
        cudaEventCreateWithFlags(&evA, cudaEventDisableTiming);
        cudaEventCreateWithFlags(&evB, cudaEventDisableTiming);
        cudaEventCreateWithFlags(&evC, cudaEventDisableTiming);
    }

    // fork: gemm1 (independent of graph structure) runs on s2
    cudaEventRecord(evA, 0);
    cudaStreamWaitEvent(s2, evA, 0);
    gemm_kernel<HID_C, 1><<<cdiv_ll(N, 128), 256, 0, s2>>>(x, W1, nullptr, N);
    cudaEventRecord(evB, s2);

    // CSR build + normalization on the main (capture) stream
    deg_cnt_kernel<<<cdiv_ll((E + 1) / 2, T), T>>>(dst, ew, E);
    scanA_kernel<<<nb, SCAN_BT>>>(N);
    scanB_kernel<<<nb, SCAN_BT>>>(N, nb);
    fill_kernel<<<cdiv_ll((E + 1) / 2, T), T>>>(src, dst, ew, E);

    // cleanup (deg/cnt dead after scanB) — off the critical path on s2
    cudaStreamWaitEvent(s2, evA, 0);
    cleanup_kernel<<<cdiv_ll(N, T), T, 0, s2>>>(N);
    cudaEventRecord(evC, s2);

    // join: gather1 needs both h1 (s2) and CSR (main)
    cudaStreamWaitEvent(0, evB, 0);
    gather_kernel<HID_C, 1><<<cdiv_ll((long long)N * 32, T), T>>>(N);

    // layer 2 + decode on main stream
    gemm_kernel<OUT_C, 2><<<cdiv_ll(N, 128), 256>>>(x, W2, b1, N);
    gather_kernel<OUT_C, 2><<<cdiv_ll((long long)N * 32, T), T>>>(N);
    decode_kernel<<<cdiv_ll((long long)EL * 32, T), T>>>(ea, eb, b2, out, EL);

    // graph end state includes cleanup
    cudaStreamWaitEvent(0, evC, 0);
}